// round 12
// baseline (speedup 1.0000x reference)
#include <cuda_runtime.h>
#include <cuda_fp16.h>
#include <mma.h>
#include <cstdint>

using namespace nvcuda;

#define IN_F   256
#define H_F    64
#define OUT_F  40
#define KSTEPS 10
#define MAX_N  50000
#define MAX_E  800000
#define SCAN_B 1024
#define MAX_BLK ((MAX_N + SCAN_B - 1) / SCAN_B)

// ---------------- scratch (device globals: no allocation allowed) ----------
__device__ __align__(16) __half g_A [MAX_N * H_F];   // ping
__device__ __align__(16) __half g_B [MAX_N * H_F];   // pong
__device__ __align__(16) __half g_h0[MAX_N * H_F];   // teleport state
__device__ __align__(16) __half g_W1h[IN_F * H_F];   // fp16 weights
__device__ __align__(16) __half g_W2h[H_F * H_F];
__device__ int   g_degi[MAX_N];
__device__ float g_dinv[MAX_N];
__device__ int   g_off [MAX_N + 1];
__device__ int   g_cur [MAX_N];
__device__ int   g_bsum[MAX_BLK];
__device__ int2  g_csr [MAX_E];    // {src row, weight bits}
__device__ int   g_idx_is64;

// ---------------- init: zero degi + reset dtype flag -----------------------
__global__ void zero_kernel(int N) {
    int i = blockIdx.x * blockDim.x + threadIdx.x;
    if (i < N) g_degi[i] = 0;
    if (i == 0) g_idx_is64 = 1;
}

// detect int64 vs int32 (odd 32-bit words all zero <=> int64) + fp16 weights.
// Runs strictly after zero_kernel (same stream) so the flag reset is ordered.
__global__ void detect_wconv_kernel(const int* __restrict__ ei32, int E,
                                    const float* __restrict__ W1,
                                    const float* __restrict__ W2) {
    int i = blockIdx.x * blockDim.x + threadIdx.x;
    int scan = (E < 100000) ? E : 100000;
    if (i < scan) {
        if (ei32[2 * i + 1] != 0) g_idx_is64 = 0;  // benign race: all write 0
    }
    if (i < IN_F * H_F) g_W1h[i] = __float2half_rn(W1[i]);
    if (i < H_F * H_F)  g_W2h[i] = __float2half_rn(W2[i]);
}

// in-degree histogram straight off the edge list (no staging)
__global__ void edge_prep_kernel(const void* __restrict__ ei_raw, int E) {
    int e = blockIdx.x * blockDim.x + threadIdx.x;
    if (e >= E) return;
    int c;
    if (g_idx_is64) c = (int)((const long long*)ei_raw)[E + e];
    else            c = ((const int*)ei_raw)[E + e];
    atomicAdd(&g_degi[c], 1);
}

// ---------------- prefix sum over degrees -> CSR offsets (+dinv fused) -----
__global__ void scan1_kernel(int N) {
    __shared__ int s[SCAN_B];
    int i = blockIdx.x * SCAN_B + threadIdx.x;
    int v = (i < N) ? g_degi[i] : 0;
    s[threadIdx.x] = v;
    __syncthreads();
    #pragma unroll
    for (int d = 1; d < SCAN_B; d <<= 1) {
        int t = (threadIdx.x >= d) ? s[threadIdx.x - d] : 0;
        __syncthreads();
        s[threadIdx.x] += t;
        __syncthreads();
    }
    if (i < N) {
        g_off[i]  = s[threadIdx.x] - v;                 // exclusive
        g_dinv[i] = rsqrtf((float)v + 1.0f);            // +1 self loop
    }
    if (threadIdx.x == SCAN_B - 1) g_bsum[blockIdx.x] = s[SCAN_B - 1];
}

__global__ void scan2_kernel(int nblk) {
    __shared__ int s[64];
    int t = threadIdx.x;
    if (nblk <= 64) {
        int v = (t < nblk) ? g_bsum[t] : 0;
        s[t] = v;
        __syncthreads();
        #pragma unroll
        for (int d = 1; d < 64; d <<= 1) {
            int u = (t >= d) ? s[t - d] : 0;
            __syncthreads();
            s[t] += u;
            __syncthreads();
        }
        if (t < nblk) g_bsum[t] = s[t] - v;   // exclusive
    } else if (t == 0) {
        int acc = 0;
        for (int b = 0; b < nblk; b++) { int u = g_bsum[b]; g_bsum[b] = acc; acc += u; }
    }
}

__global__ void scan3_kernel(int N, int E) {
    int i = blockIdx.x * blockDim.x + threadIdx.x;
    if (i < N) {
        int o = g_off[i] + g_bsum[i >> 10];
        g_off[i] = o;
        g_cur[i] = o;
    }
    if (i == 0) g_off[N] = E;
}

// ---------------- CSR placement (re-reads edge list; L2-hot) ---------------
__global__ void place_kernel(const void* __restrict__ ei_raw, int E) {
    int e = blockIdx.x * blockDim.x + threadIdx.x;
    if (e >= E) return;
    int r, c;
    if (g_idx_is64) {
        const long long* ei = (const long long*)ei_raw;
        r = (int)ei[e];
        c = (int)ei[E + e];
    } else {
        const int* ei = (const int*)ei_raw;
        r = ei[e];
        c = ei[E + e];
    }
    int pos = atomicAdd(&g_cur[c], 1);
    float w = g_dinv[r] * g_dinv[c];
    g_csr[pos] = make_int2(r, __float_as_int(w));
}

// ---------------- encode (tensor cores): h0 = relu(x@W1+b1)@W2+b2 ----------
#define XS_LD (IN_F + 8)
#define TS_LD (H_F + 8)
__global__ __launch_bounds__(256) void encode_kernel(
    const float* __restrict__ x,
    const float* __restrict__ b1, const float* __restrict__ b2,
    int N)
{
    __shared__ __align__(16) __half xs[64 * XS_LD];   // 33792 B
    __shared__ __align__(16) __half ts[64 * TS_LD];   // 9216 B
    float* os = reinterpret_cast<float*>(xs);          // 18432 B alias

    int tid  = threadIdx.x;
    int wid  = tid >> 5;
    int row0 = blockIdx.x * 64;

    for (int i = tid; i < 64 * (IN_F / 4); i += 256) {
        int r  = i >> 6;
        int k4 = i & 63;
        float4 v = make_float4(0.f, 0.f, 0.f, 0.f);
        if (row0 + r < N)
            v = ((const float4*)x)[(size_t)(row0 + r) * (IN_F / 4) + k4];
        __half2 h0 = __floats2half2_rn(v.x, v.y);
        __half2 h1 = __floats2half2_rn(v.z, v.w);
        uint2 pk;
        pk.x = *reinterpret_cast<unsigned*>(&h0);
        pk.y = *reinterpret_cast<unsigned*>(&h1);
        *reinterpret_cast<uint2*>(&xs[r * XS_LD + k4 * 4]) = pk;
    }
    __syncthreads();

    int ct = wid & 3;
    int rt = wid >> 2;

    wmma::fragment<wmma::matrix_a, 16, 16, 16, __half, wmma::row_major> a0, a1;
    wmma::fragment<wmma::matrix_b, 16, 16, 16, __half, wmma::row_major> b;
    wmma::fragment<wmma::accumulator, 16, 16, 16, float> c0, c1;

    wmma::fill_fragment(c0, 0.0f);
    wmma::fill_fragment(c1, 0.0f);
    for (int k = 0; k < IN_F; k += 16) {
        wmma::load_matrix_sync(b, &g_W1h[k * H_F + ct * 16], H_F);
        wmma::load_matrix_sync(a0, &xs[(rt * 16) * XS_LD + k], XS_LD);
        wmma::mma_sync(c0, a0, b, c0);
        wmma::load_matrix_sync(a1, &xs[((rt + 2) * 16) * XS_LD + k], XS_LD);
        wmma::mma_sync(c1, a1, b, c1);
    }
    __syncthreads();
    wmma::store_matrix_sync(&os[(rt * 16) * TS_LD + ct * 16], c0, TS_LD, wmma::mem_row_major);
    wmma::store_matrix_sync(&os[((rt + 2) * 16) * TS_LD + ct * 16], c1, TS_LD, wmma::mem_row_major);
    __syncthreads();
    for (int i = tid; i < 64 * H_F; i += 256) {
        int r = i >> 6;
        int c = i & 63;
        float v = os[r * TS_LD + c] + __ldg(&b1[c]);
        ts[r * TS_LD + c] = __float2half_rn(fmaxf(v, 0.0f));
    }
    __syncthreads();

    wmma::fill_fragment(c0, 0.0f);
    wmma::fill_fragment(c1, 0.0f);
    for (int k = 0; k < H_F; k += 16) {
        wmma::load_matrix_sync(b, &g_W2h[k * H_F + ct * 16], H_F);
        wmma::load_matrix_sync(a0, &ts[(rt * 16) * TS_LD + k], TS_LD);
        wmma::mma_sync(c0, a0, b, c0);
        wmma::load_matrix_sync(a1, &ts[((rt + 2) * 16) * TS_LD + k], TS_LD);
        wmma::mma_sync(c1, a1, b, c1);
    }
    __syncthreads();
    wmma::store_matrix_sync(&os[(rt * 16) * TS_LD + ct * 16], c0, TS_LD, wmma::mem_row_major);
    wmma::store_matrix_sync(&os[((rt + 2) * 16) * TS_LD + ct * 16], c1, TS_LD, wmma::mem_row_major);
    __syncthreads();

    for (int i = tid; i < 64 * (H_F / 4); i += 256) {
        int r  = i >> 4;
        int c4 = (i & 15) * 4;
        int gr = row0 + r;
        if (gr >= N) continue;
        float v0 = os[r * TS_LD + c4 + 0] + __ldg(&b2[c4 + 0]);
        float v1 = os[r * TS_LD + c4 + 1] + __ldg(&b2[c4 + 1]);
        float v2 = os[r * TS_LD + c4 + 2] + __ldg(&b2[c4 + 2]);
        float v3 = os[r * TS_LD + c4 + 3] + __ldg(&b2[c4 + 3]);
        __half2 p0 = __floats2half2_rn(v0, v1);
        __half2 p1 = __floats2half2_rn(v2, v3);
        uint2 pk;
        pk.x = *reinterpret_cast<unsigned*>(&p0);
        pk.y = *reinterpret_cast<unsigned*>(&p1);
        *reinterpret_cast<uint2*>(&g_A [(size_t)gr * H_F + c4]) = pk;
        *reinterpret_cast<uint2*>(&g_h0[(size_t)gr * H_F + c4]) = pk;
    }
}

// ---------------- fused gather+combine step: one WARP per node -------------
// 32 lanes x 4 B = one 128 B source row per edge (single wavefront), no
// intra-warp degree divergence, csr reads warp-broadcast, 4-way unroll for
// MLP. fp32 accumulate, fp16 store. Per-step launches keep L1 usable.
template<int DIR>
__global__ __launch_bounds__(256) void gather_kernel(int N) {
    const __half* src = DIR ? g_B : g_A;
    __half*       dst = DIR ? g_A : g_B;

    int gw   = (blockIdx.x * blockDim.x + threadIdx.x) >> 5;   // warp id = node
    if (gw >= N) return;
    int lane = threadIdx.x & 31;
    int node = gw;

    const unsigned* srcv = (const unsigned*)src;   // row r lane l -> srcv[r*32+l]
    int beg = __ldg(&g_off[node]);
    int end = __ldg(&g_off[node + 1]);

    // hoist self/h0/dinv loads above the edge loop (overlap latency)
    unsigned selfp = __ldg(&srcv[(size_t)node * 32 + lane]);
    unsigned h0p   = __ldg(&((const unsigned*)g_h0)[(size_t)node * 32 + lane]);
    float s = __ldg(&g_dinv[node]);

    float2 acc = make_float2(0.f, 0.f);
    int j = beg;
    for (; j + 4 <= end; j += 4) {
        int2 rw0 = __ldg(&g_csr[j]);
        int2 rw1 = __ldg(&g_csr[j + 1]);
        int2 rw2 = __ldg(&g_csr[j + 2]);
        int2 rw3 = __ldg(&g_csr[j + 3]);
        unsigned p0 = __ldg(&srcv[(size_t)rw0.x * 32 + lane]);
        unsigned p1 = __ldg(&srcv[(size_t)rw1.x * 32 + lane]);
        unsigned p2 = __ldg(&srcv[(size_t)rw2.x * 32 + lane]);
        unsigned p3 = __ldg(&srcv[(size_t)rw3.x * 32 + lane]);
        float2 f0 = __half22float2(*reinterpret_cast<__half2*>(&p0));
        float2 f1 = __half22float2(*reinterpret_cast<__half2*>(&p1));
        float2 f2 = __half22float2(*reinterpret_cast<__half2*>(&p2));
        float2 f3 = __half22float2(*reinterpret_cast<__half2*>(&p3));
        float w0 = __int_as_float(rw0.y);
        float w1 = __int_as_float(rw1.y);
        float w2 = __int_as_float(rw2.y);
        float w3 = __int_as_float(rw3.y);
        acc.x += w0 * f0.x + w1 * f1.x + w2 * f2.x + w3 * f3.x;
        acc.y += w0 * f0.y + w1 * f1.y + w2 * f2.y + w3 * f3.y;
    }
    for (; j < end; j++) {
        int2 rw = __ldg(&g_csr[j]);
        unsigned p = __ldg(&srcv[(size_t)rw.x * 32 + lane]);
        float2 f = __half22float2(*reinterpret_cast<__half2*>(&p));
        float w = __int_as_float(rw.y);
        acc.x += w * f.x;
        acc.y += w * f.y;
    }

    float sw = s * s;
    float2 sf = __half22float2(*reinterpret_cast<__half2*>(&selfp));
    float2 hf = __half22float2(*reinterpret_cast<__half2*>(&h0p));
    float ox = 0.9f * (acc.x + sw * sf.x) + 0.1f * hf.x;
    float oy = 0.9f * (acc.y + sw * sf.y) + 0.1f * hf.y;
    __half2 op = __floats2half2_rn(ox, oy);
    ((unsigned*)dst)[(size_t)node * 32 + lane] = *reinterpret_cast<unsigned*>(&op);
}

// ---------------- decode: out = h @ Wf + bf --------------------------------
__device__ __forceinline__ void h8_to_f8d(uint4 p, float4& lo, float4& hi) {
    float2 f0 = __half22float2(*reinterpret_cast<__half2*>(&p.x));
    float2 f1 = __half22float2(*reinterpret_cast<__half2*>(&p.y));
    float2 f2 = __half22float2(*reinterpret_cast<__half2*>(&p.z));
    float2 f3 = __half22float2(*reinterpret_cast<__half2*>(&p.w));
    lo = make_float4(f0.x, f0.y, f1.x, f1.y);
    hi = make_float4(f2.x, f2.y, f3.x, f3.y);
}
__global__ __launch_bounds__(256) void decode_kernel(
    const float* __restrict__ Wf, const float* __restrict__ bf,
    float* __restrict__ out, int N)
{
    __shared__ float hs[32][H_F];
    __shared__ float wfs[H_F * OUT_F];
    __shared__ float bfs[OUT_F];
    int tid  = threadIdx.x;
    int row0 = blockIdx.x * 32;

    for (int i = tid; i < H_F * OUT_F; i += 256) wfs[i] = Wf[i];
    if (tid < OUT_F) bfs[tid] = bf[tid];
    for (int i = tid; i < 32 * 8; i += 256) {
        int r  = i >> 3;
        int k8 = i & 7;
        float4 lo = make_float4(0.f, 0.f, 0.f, 0.f), hi = lo;
        if (row0 + r < N)
            h8_to_f8d(((const uint4*)g_A)[(size_t)(row0 + r) * 8 + k8], lo, hi);
        *(float4*)&hs[r][k8 * 8]     = lo;
        *(float4*)&hs[r][k8 * 8 + 4] = hi;
    }
    __syncthreads();

    for (int e = tid; e < 32 * OUT_F; e += 256) {
        int r = e / OUT_F;
        int o = e % OUT_F;
        if (row0 + r >= N) continue;
        float acc = bfs[o];
        #pragma unroll
        for (int k = 0; k < H_F; k++) acc += hs[r][k] * wfs[k * OUT_F + o];
        out[(size_t)(row0 + r) * OUT_F + o] = acc;
    }
}

// ---------------- launch ---------------------------------------------------
extern "C" void kernel_launch(void* const* d_in, const int* in_sizes, int n_in,
                              void* d_out, int out_size) {
    const float* x  = (const float*)d_in[0];
    const void*  ei = d_in[1];
    const float* W1 = (const float*)d_in[2];
    const float* b1 = (const float*)d_in[3];
    const float* W2 = (const float*)d_in[4];
    const float* b2 = (const float*)d_in[5];
    const float* Wf = (const float*)d_in[6];
    const float* bf = (const float*)d_in[7];
    float* out = (float*)d_out;

    int N = in_sizes[0] / IN_F;   // 50000
    int E = in_sizes[1] / 2;      // 800000
    int nblk = (N + SCAN_B - 1) / SCAN_B;

    zero_kernel<<<(N + 255) / 256, 256>>>(N);
    detect_wconv_kernel<<<(100000 + 255) / 256, 256>>>((const int*)ei, E, W1, W2);
    edge_prep_kernel<<<(E + 255) / 256, 256>>>(ei, E);
    scan1_kernel<<<nblk, SCAN_B>>>(N);
    scan2_kernel<<<1, 64>>>(nblk);
    scan3_kernel<<<(N + 255) / 256, 256>>>(N, E);
    place_kernel<<<(E + 255) / 256, 256>>>(ei, E);

    encode_kernel<<<(N + 63) / 64, 256>>>(x, b1, b2, N);

    int gat_blocks = (N * 32 + 255) / 256;   // one warp per node
    for (int k = 0; k < KSTEPS; k += 2) {
        gather_kernel<0><<<gat_blocks, 256>>>(N);   // A -> B
        gather_kernel<1><<<gat_blocks, 256>>>(N);   // B -> A
    }

    decode_kernel<<<(N + 31) / 32, 256>>>(Wf, bf, out, N);
}

// round 13
// speedup vs baseline: 1.1929x; 1.1929x over previous
#include <cuda_runtime.h>
#include <cuda_fp16.h>
#include <mma.h>
#include <cstdint>

using namespace nvcuda;

#define IN_F   256
#define H_F    64
#define OUT_F  40
#define KSTEPS 10
#define MAX_N  50000
#define MAX_E  800000
#define SCAN_B 1024
#define MAX_BLK ((MAX_N + SCAN_B - 1) / SCAN_B)

// ---------------- scratch (device globals: no allocation allowed) ----------
__device__ __align__(16) __half g_A [MAX_N * H_F];   // ping
__device__ __align__(16) __half g_B [MAX_N * H_F];   // pong
__device__ __align__(16) __half g_h0[MAX_N * H_F];   // teleport state
__device__ __align__(16) __half g_W1h[IN_F * H_F];   // fp16 weights
__device__ __align__(16) __half g_W2h[H_F * H_F];
__device__ int   g_degi[MAX_N];
__device__ float g_dinv[MAX_N];
__device__ int   g_off [MAX_N + 1];
__device__ int   g_cur [MAX_N];
__device__ int   g_bsum[MAX_BLK];
__device__ int2  g_csr [MAX_E];    // {src row, weight bits}
__device__ int   g_idx_is64;

// ---------------- fp16 helpers ---------------------------------------------
__device__ __forceinline__ void accum8(float4& lo, float4& hi, uint4 p, float w) {
    float2 f0 = __half22float2(*reinterpret_cast<__half2*>(&p.x));
    float2 f1 = __half22float2(*reinterpret_cast<__half2*>(&p.y));
    float2 f2 = __half22float2(*reinterpret_cast<__half2*>(&p.z));
    float2 f3 = __half22float2(*reinterpret_cast<__half2*>(&p.w));
    lo.x += w * f0.x; lo.y += w * f0.y; lo.z += w * f1.x; lo.w += w * f1.y;
    hi.x += w * f2.x; hi.y += w * f2.y; hi.z += w * f3.x; hi.w += w * f3.y;
}
__device__ __forceinline__ void h8_to_f8(uint4 p, float4& lo, float4& hi) {
    float2 f0 = __half22float2(*reinterpret_cast<__half2*>(&p.x));
    float2 f1 = __half22float2(*reinterpret_cast<__half2*>(&p.y));
    float2 f2 = __half22float2(*reinterpret_cast<__half2*>(&p.z));
    float2 f3 = __half22float2(*reinterpret_cast<__half2*>(&p.w));
    lo = make_float4(f0.x, f0.y, f1.x, f1.y);
    hi = make_float4(f2.x, f2.y, f3.x, f3.y);
}
__device__ __forceinline__ uint4 f8_to_h8(float4 lo, float4 hi) {
    __half2 h0 = __floats2half2_rn(lo.x, lo.y);
    __half2 h1 = __floats2half2_rn(lo.z, lo.w);
    __half2 h2 = __floats2half2_rn(hi.x, hi.y);
    __half2 h3 = __floats2half2_rn(hi.z, hi.w);
    uint4 r;
    r.x = *reinterpret_cast<unsigned*>(&h0);
    r.y = *reinterpret_cast<unsigned*>(&h1);
    r.z = *reinterpret_cast<unsigned*>(&h2);
    r.w = *reinterpret_cast<unsigned*>(&h3);
    return r;
}

// ---------------- init: zero degi + reset dtype flag -----------------------
__global__ void zero_kernel(int N) {
    int i = blockIdx.x * blockDim.x + threadIdx.x;
    if (i < N) g_degi[i] = 0;
    if (i == 0) g_idx_is64 = 1;
}

// detect int64 vs int32 (odd 32-bit words all zero <=> int64) + fp16 weights.
// Runs strictly after zero_kernel (same stream) so the flag reset is ordered.
__global__ void detect_wconv_kernel(const int* __restrict__ ei32, int E,
                                    const float* __restrict__ W1,
                                    const float* __restrict__ W2) {
    int i = blockIdx.x * blockDim.x + threadIdx.x;
    int scan = (E < 100000) ? E : 100000;
    if (i < scan) {
        if (ei32[2 * i + 1] != 0) g_idx_is64 = 0;  // benign race: all write 0
    }
    if (i < IN_F * H_F) g_W1h[i] = __float2half_rn(W1[i]);
    if (i < H_F * H_F)  g_W2h[i] = __float2half_rn(W2[i]);
}

// in-degree histogram straight off the edge list (no staging array)
__global__ void edge_prep_kernel(const void* __restrict__ ei_raw, int E) {
    int e = blockIdx.x * blockDim.x + threadIdx.x;
    if (e >= E) return;
    int c;
    if (g_idx_is64) c = (int)((const long long*)ei_raw)[E + e];
    else            c = ((const int*)ei_raw)[E + e];
    atomicAdd(&g_degi[c], 1);
}

// ---------------- prefix sum over degrees -> CSR offsets (+dinv fused) -----
__global__ void scan1_kernel(int N) {
    __shared__ int s[SCAN_B];
    int i = blockIdx.x * SCAN_B + threadIdx.x;
    int v = (i < N) ? g_degi[i] : 0;
    s[threadIdx.x] = v;
    __syncthreads();
    #pragma unroll
    for (int d = 1; d < SCAN_B; d <<= 1) {
        int t = (threadIdx.x >= d) ? s[threadIdx.x - d] : 0;
        __syncthreads();
        s[threadIdx.x] += t;
        __syncthreads();
    }
    if (i < N) {
        g_off[i]  = s[threadIdx.x] - v;                 // exclusive
        g_dinv[i] = rsqrtf((float)v + 1.0f);            // +1 self loop
    }
    if (threadIdx.x == SCAN_B - 1) g_bsum[blockIdx.x] = s[SCAN_B - 1];
}

__global__ void scan2_kernel(int nblk) {
    __shared__ int s[64];
    int t = threadIdx.x;
    if (nblk <= 64) {
        int v = (t < nblk) ? g_bsum[t] : 0;
        s[t] = v;
        __syncthreads();
        #pragma unroll
        for (int d = 1; d < 64; d <<= 1) {
            int u = (t >= d) ? s[t - d] : 0;
            __syncthreads();
            s[t] += u;
            __syncthreads();
        }
        if (t < nblk) g_bsum[t] = s[t] - v;   // exclusive
    } else if (t == 0) {
        int acc = 0;
        for (int b = 0; b < nblk; b++) { int u = g_bsum[b]; g_bsum[b] = acc; acc += u; }
    }
}

__global__ void scan3_kernel(int N, int E) {
    int i = blockIdx.x * blockDim.x + threadIdx.x;
    if (i < N) {
        int o = g_off[i] + g_bsum[i >> 10];
        g_off[i] = o;
        g_cur[i] = o;
    }
    if (i == 0) g_off[N] = E;
}

// ---------------- CSR placement (re-reads edge list; L2-hot) ---------------
__global__ void place_kernel(const void* __restrict__ ei_raw, int E) {
    int e = blockIdx.x * blockDim.x + threadIdx.x;
    if (e >= E) return;
    int r, c;
    if (g_idx_is64) {
        const long long* ei = (const long long*)ei_raw;
        r = (int)ei[e];
        c = (int)ei[E + e];
    } else {
        const int* ei = (const int*)ei_raw;
        r = ei[e];
        c = ei[E + e];
    }
    int pos = atomicAdd(&g_cur[c], 1);
    float w = g_dinv[r] * g_dinv[c];
    g_csr[pos] = make_int2(r, __float_as_int(w));
}

// ---------------- encode (tensor cores): h0 = relu(x@W1+b1)@W2+b2 ----------
#define XS_LD (IN_F + 8)
#define TS_LD (H_F + 8)
__global__ __launch_bounds__(256) void encode_kernel(
    const float* __restrict__ x,
    const float* __restrict__ b1, const float* __restrict__ b2,
    int N)
{
    __shared__ __align__(16) __half xs[64 * XS_LD];   // 33792 B
    __shared__ __align__(16) __half ts[64 * TS_LD];   // 9216 B
    float* os = reinterpret_cast<float*>(xs);          // 18432 B alias

    int tid  = threadIdx.x;
    int wid  = tid >> 5;
    int row0 = blockIdx.x * 64;

    for (int i = tid; i < 64 * (IN_F / 4); i += 256) {
        int r  = i >> 6;
        int k4 = i & 63;
        float4 v = make_float4(0.f, 0.f, 0.f, 0.f);
        if (row0 + r < N)
            v = ((const float4*)x)[(size_t)(row0 + r) * (IN_F / 4) + k4];
        __half2 h0 = __floats2half2_rn(v.x, v.y);
        __half2 h1 = __floats2half2_rn(v.z, v.w);
        uint2 pk;
        pk.x = *reinterpret_cast<unsigned*>(&h0);
        pk.y = *reinterpret_cast<unsigned*>(&h1);
        *reinterpret_cast<uint2*>(&xs[r * XS_LD + k4 * 4]) = pk;
    }
    __syncthreads();

    int ct = wid & 3;
    int rt = wid >> 2;

    wmma::fragment<wmma::matrix_a, 16, 16, 16, __half, wmma::row_major> a0, a1;
    wmma::fragment<wmma::matrix_b, 16, 16, 16, __half, wmma::row_major> b;
    wmma::fragment<wmma::accumulator, 16, 16, 16, float> c0, c1;

    wmma::fill_fragment(c0, 0.0f);
    wmma::fill_fragment(c1, 0.0f);
    for (int k = 0; k < IN_F; k += 16) {
        wmma::load_matrix_sync(b, &g_W1h[k * H_F + ct * 16], H_F);
        wmma::load_matrix_sync(a0, &xs[(rt * 16) * XS_LD + k], XS_LD);
        wmma::mma_sync(c0, a0, b, c0);
        wmma::load_matrix_sync(a1, &xs[((rt + 2) * 16) * XS_LD + k], XS_LD);
        wmma::mma_sync(c1, a1, b, c1);
    }
    __syncthreads();
    wmma::store_matrix_sync(&os[(rt * 16) * TS_LD + ct * 16], c0, TS_LD, wmma::mem_row_major);
    wmma::store_matrix_sync(&os[((rt + 2) * 16) * TS_LD + ct * 16], c1, TS_LD, wmma::mem_row_major);
    __syncthreads();
    for (int i = tid; i < 64 * H_F; i += 256) {
        int r = i >> 6;
        int c = i & 63;
        float v = os[r * TS_LD + c] + __ldg(&b1[c]);
        ts[r * TS_LD + c] = __float2half_rn(fmaxf(v, 0.0f));
    }
    __syncthreads();

    wmma::fill_fragment(c0, 0.0f);
    wmma::fill_fragment(c1, 0.0f);
    for (int k = 0; k < H_F; k += 16) {
        wmma::load_matrix_sync(b, &g_W2h[k * H_F + ct * 16], H_F);
        wmma::load_matrix_sync(a0, &ts[(rt * 16) * TS_LD + k], TS_LD);
        wmma::mma_sync(c0, a0, b, c0);
        wmma::load_matrix_sync(a1, &ts[((rt + 2) * 16) * TS_LD + k], TS_LD);
        wmma::mma_sync(c1, a1, b, c1);
    }
    __syncthreads();
    wmma::store_matrix_sync(&os[(rt * 16) * TS_LD + ct * 16], c0, TS_LD, wmma::mem_row_major);
    wmma::store_matrix_sync(&os[((rt + 2) * 16) * TS_LD + ct * 16], c1, TS_LD, wmma::mem_row_major);
    __syncthreads();

    for (int i = tid; i < 64 * (H_F / 4); i += 256) {
        int r  = i >> 4;
        int c4 = (i & 15) * 4;
        int gr = row0 + r;
        if (gr >= N) continue;
        float v0 = os[r * TS_LD + c4 + 0] + __ldg(&b2[c4 + 0]);
        float v1 = os[r * TS_LD + c4 + 1] + __ldg(&b2[c4 + 1]);
        float v2 = os[r * TS_LD + c4 + 2] + __ldg(&b2[c4 + 2]);
        float v3 = os[r * TS_LD + c4 + 3] + __ldg(&b2[c4 + 3]);
        __half2 p0 = __floats2half2_rn(v0, v1);
        __half2 p1 = __floats2half2_rn(v2, v3);
        uint2 pk;
        pk.x = *reinterpret_cast<unsigned*>(&p0);
        pk.y = *reinterpret_cast<unsigned*>(&p1);
        *reinterpret_cast<uint2*>(&g_A [(size_t)gr * H_F + c4]) = pk;
        *reinterpret_cast<uint2*>(&g_h0[(size_t)gr * H_F + c4]) = pk;
    }
}

// ---------------- fused gather+combine propagation step --------------------
// R9-proven layout: 8 threads per node, uint4 (16 B) per lane, 4 node-streams
// per warp. 4-way unroll (~50 regs) + minBlocksPerSM=4 -> 32 warps/SM to
// raise outstanding-load count. fp32 accumulate, fp16 store.
template<int DIR>
__global__ __launch_bounds__(256, 4) void gather_kernel(int N) {
    const __half* src = DIR ? g_B : g_A;
    __half*       dst = DIR ? g_A : g_B;

    int idx  = blockIdx.x * blockDim.x + threadIdx.x;
    int node = idx >> 3;
    if (node >= N) return;
    int lane = idx & 7;                        // 16B chunk 0..7

    const uint4* srcv = (const uint4*)src;
    int beg = __ldg(&g_off[node]);
    int end = __ldg(&g_off[node + 1]);

    float4 alo = make_float4(0.f, 0.f, 0.f, 0.f);
    float4 ahi = make_float4(0.f, 0.f, 0.f, 0.f);

    int j = beg;
    int stop4 = beg + ((end - beg) & ~3);
    for (; j < stop4; j += 4) {
        int2 rw0 = __ldg(&g_csr[j]);
        int2 rw1 = __ldg(&g_csr[j + 1]);
        int2 rw2 = __ldg(&g_csr[j + 2]);
        int2 rw3 = __ldg(&g_csr[j + 3]);
        uint4 p0 = __ldg(&srcv[(size_t)rw0.x * 8 + lane]);
        uint4 p1 = __ldg(&srcv[(size_t)rw1.x * 8 + lane]);
        uint4 p2 = __ldg(&srcv[(size_t)rw2.x * 8 + lane]);
        uint4 p3 = __ldg(&srcv[(size_t)rw3.x * 8 + lane]);
        accum8(alo, ahi, p0, __int_as_float(rw0.y));
        accum8(alo, ahi, p1, __int_as_float(rw1.y));
        accum8(alo, ahi, p2, __int_as_float(rw2.y));
        accum8(alo, ahi, p3, __int_as_float(rw3.y));
    }
    for (; j < end; j++) {
        int2 rw = __ldg(&g_csr[j]);
        uint4 p = __ldg(&srcv[(size_t)rw.x * 8 + lane]);
        accum8(alo, ahi, p, __int_as_float(rw.y));
    }

    float s  = __ldg(&g_dinv[node]);
    float sw = s * s;
    float4 slo, shi, hlo, hhi;
    h8_to_f8(__ldg(&srcv[(size_t)node * 8 + lane]), slo, shi);
    h8_to_f8(__ldg(&((const uint4*)g_h0)[(size_t)node * 8 + lane]), hlo, hhi);
    float4 olo, ohi;
    olo.x = 0.9f * (alo.x + sw * slo.x) + 0.1f * hlo.x;
    olo.y = 0.9f * (alo.y + sw * slo.y) + 0.1f * hlo.y;
    olo.z = 0.9f * (alo.z + sw * slo.z) + 0.1f * hlo.z;
    olo.w = 0.9f * (alo.w + sw * slo.w) + 0.1f * hlo.w;
    ohi.x = 0.9f * (ahi.x + sw * shi.x) + 0.1f * hhi.x;
    ohi.y = 0.9f * (ahi.y + sw * shi.y) + 0.1f * hhi.y;
    ohi.z = 0.9f * (ahi.z + sw * shi.z) + 0.1f * hhi.z;
    ohi.w = 0.9f * (ahi.w + sw * shi.w) + 0.1f * hhi.w;
    ((uint4*)dst)[(size_t)node * 8 + lane] = f8_to_h8(olo, ohi);
}

// ---------------- decode: out = h @ Wf + bf --------------------------------
__global__ __launch_bounds__(256) void decode_kernel(
    const float* __restrict__ Wf, const float* __restrict__ bf,
    float* __restrict__ out, int N)
{
    __shared__ float hs[32][H_F];
    __shared__ float wfs[H_F * OUT_F];
    __shared__ float bfs[OUT_F];
    int tid  = threadIdx.x;
    int row0 = blockIdx.x * 32;

    for (int i = tid; i < H_F * OUT_F; i += 256) wfs[i] = Wf[i];
    if (tid < OUT_F) bfs[tid] = bf[tid];
    for (int i = tid; i < 32 * 8; i += 256) {
        int r  = i >> 3;
        int k8 = i & 7;
        float4 lo = make_float4(0.f, 0.f, 0.f, 0.f), hi = lo;
        if (row0 + r < N)
            h8_to_f8(((const uint4*)g_A)[(size_t)(row0 + r) * 8 + k8], lo, hi);
        *(float4*)&hs[r][k8 * 8]     = lo;
        *(float4*)&hs[r][k8 * 8 + 4] = hi;
    }
    __syncthreads();

    for (int e = tid; e < 32 * OUT_F; e += 256) {
        int r = e / OUT_F;
        int o = e % OUT_F;
        if (row0 + r >= N) continue;
        float acc = bfs[o];
        #pragma unroll
        for (int k = 0; k < H_F; k++) acc += hs[r][k] * wfs[k * OUT_F + o];
        out[(size_t)(row0 + r) * OUT_F + o] = acc;
    }
}

// ---------------- launch ---------------------------------------------------
extern "C" void kernel_launch(void* const* d_in, const int* in_sizes, int n_in,
                              void* d_out, int out_size) {
    const float* x  = (const float*)d_in[0];
    const void*  ei = d_in[1];
    const float* W1 = (const float*)d_in[2];
    const float* b1 = (const float*)d_in[3];
    const float* W2 = (const float*)d_in[4];
    const float* b2 = (const float*)d_in[5];
    const float* Wf = (const float*)d_in[6];
    const float* bf = (const float*)d_in[7];
    float* out = (float*)d_out;

    int N = in_sizes[0] / IN_F;   // 50000
    int E = in_sizes[1] / 2;      // 800000
    int nblk = (N + SCAN_B - 1) / SCAN_B;

    zero_kernel<<<(N + 255) / 256, 256>>>(N);
    detect_wconv_kernel<<<(100000 + 255) / 256, 256>>>((const int*)ei, E, W1, W2);
    edge_prep_kernel<<<(E + 255) / 256, 256>>>(ei, E);
    scan1_kernel<<<nblk, SCAN_B>>>(N);
    scan2_kernel<<<1, 64>>>(nblk);
    scan3_kernel<<<(N + 255) / 256, 256>>>(N, E);
    place_kernel<<<(E + 255) / 256, 256>>>(ei, E);

    encode_kernel<<<(N + 63) / 64, 256>>>(x, b1, b2, N);

    int gat_blocks = (N * 8 + 255) / 256;
    for (int k = 0; k < KSTEPS; k += 2) {
        gather_kernel<0><<<gat_blocks, 256>>>(N);   // A -> B
        gather_kernel<1><<<gat_blocks, 256>>>(N);   // B -> A
    }

    decode_kernel<<<(N + 31) / 32, 256>>>(Wf, bf, out, N);
}